// round 15
// baseline (speedup 1.0000x reference)
#include <cuda_runtime.h>
#include <math.h>
#include <stdint.h>

// Problem constants: B=8192 rows, H=4096 hidden, E=8 experts, TOP_K=2. fp32.
#define B_ROWS 8192
#define HDIM   4096
#define RPB    128          // rows per gate block
#define GSZ    8            // rows per pipeline group
#define NG     (RPB / GSZ)  // 16 groups

// Dynamic smem: 2 slots x 8 rows x 8KB + s_part + 2 full-mbarriers
#define SM_TILE_BYTES  (2 * GSZ * 8192)                // 131072
#define SM_PART_OFF    SM_TILE_BYTES
#define SM_PART_BYTES  (2 * 8 * 16 * 9 * 4)            // 9216
#define SM_MBAR_OFF    (SM_PART_OFF + SM_PART_BYTES)   // 140288 (8-aligned)
#define SMEM_BYTES     (SM_MBAR_OFF + 2 * 8)

// Partial gate scores: g_part[row*16 + half*8 + e]  (half = which H-2048 slice)
__device__ float g_part[(size_t)B_ROWS * 16];

// Packed f32x2 helpers (sm_10x packed fp32 pipe, PTX-only)
#define FMA2(d, a, b, c) asm("fma.rn.f32x2 %0, %1, %2, %3;" : "=l"(d) : "l"(a), "l"(b), "l"(c))
#define ADD2(d, a, b)    asm("add.rn.f32x2 %0, %1, %2;"     : "=l"(d) : "l"(a), "l"(b))
#define PACK2(d, x)      asm("mov.b64 %0, {%1, %1};"        : "=l"(d) : "r"(x))
#define UNPK2(lo, hi, s) asm("mov.b64 {%0, %1}, %2;"        : "=r"(lo), "=r"(hi) : "l"(s))

// mbarrier / bulk-copy PTX
#define MBAR_INIT(a, n) \
    asm volatile("mbarrier.init.shared.b64 [%0], %1;" :: "r"(a), "r"(n) : "memory")
#define MBAR_EXPECT_TX(a, n) \
    asm volatile("mbarrier.arrive.expect_tx.shared.b64 _, [%0], %1;" :: "r"(a), "r"(n) : "memory")
#define MBAR_WAIT(a, par) do {                                                   \
    asm volatile(                                                                \
        "{\n\t.reg .pred P1;\n\t"                                                \
        "WL_%=:\n\t"                                                             \
        "mbarrier.try_wait.parity.acquire.cta.shared::cta.b64 P1, [%0], %1, 0x989680;\n\t" \
        "@P1 bra.uni WD_%=;\n\t"                                                 \
        "bra.uni WL_%=;\n\t"                                                     \
        "WD_%=:\n\t}"                                                            \
        :: "r"(a), "r"(par) : "memory");                                         \
} while (0)
#define BULK_G2S(dst, src, bytes, mbar) \
    asm volatile("cp.async.bulk.shared::cta.global.mbarrier::complete_tx::bytes " \
                 "[%0], [%1], %2, [%3];" \
                 :: "r"(dst), "l"(src), "r"(bytes), "r"(mbar) : "memory")

static __device__ __forceinline__ uint32_t smem_u32(const void* p) {
    uint32_t a;
    asm("{ .reg .u64 t; cvta.to.shared.u64 t, %1; cvt.u32.u64 %0, t; }" : "=r"(a) : "l"(p));
    return a;
}

// ---------------------------------------------------------------------------
// Kernel 1: gate partials. grid = 128 blocks x 512 threads (single wave).
// Block (g*2 + half) owns rows [g*128, +128) and H-half [half*2048, +2048).
//
// Pipeline (vs R14): groups of 8 rows, 2 slots x 64KB ring, and NO producer
// warp. Thread 0 issues the cp.async.bulk refill for group g+2 immediately
// after the group barrier — the barrier itself proves the slot was fully
// consumed, so empty-mbarriers disappear and the block is exactly 512
// threads (16 warps, 4/SMSP, plain __syncthreads). The per-group serial
// overhead (full-wait + barrier + stage-2) now amortizes over 8 rows.
//
// Consumers: thread t owns h = half*2048 + 4t..+3; its 32 gate weights live
// in 16 packed f32x2 registers, loaded once. Per group: 2 sub-batches of 4
// rows (FMA 16 chains, then level-0/1 shfl compress to 1 packed reg/row to
// bound register pressure), then 8 interleaved tree finishes (ILP-8),
// s_part (double-buffered by slot), __syncthreads, refill issue, stage-2:
// 64 (row,expert) reductions spread 4-per-warp -> g_part.
// ---------------------------------------------------------------------------
__global__ __launch_bounds__(512, 1) void gate_kernel(
    const float* __restrict__ hidden,
    const float* __restrict__ gw)     // (H, E) row-major
{
    extern __shared__ __align__(16) unsigned char dynsmem[];
    float* s_tile = reinterpret_cast<float*>(dynsmem);               // [16][2048]
    float* s_part = reinterpret_cast<float*>(dynsmem + SM_PART_OFF); // [2][8][16][9]

    const int t    = threadIdx.x;
    const int half = (int)blockIdx.x & 1;
    const int base_row = ((int)blockIdx.x >> 1) * RPB;

    const uint32_t mb    = smem_u32(dynsmem + SM_MBAR_OFF);  // full[0..1]
    const uint32_t tile0 = smem_u32(dynsmem);
    const char* src = reinterpret_cast<const char*>(
        hidden + (size_t)base_row * HDIM + (size_t)half * 2048);

    if (t == 0) {
        MBAR_INIT(mb + 0, 1);
        MBAR_INIT(mb + 8, 1);
        asm volatile("fence.proxy.async.shared::cta;" ::: "memory");
    }
    __syncthreads();

    // Prologue: thread 0 issues groups 0 and 1 (slots 0 and 1).
    if (t == 0) {
#pragma unroll
        for (int g0 = 0; g0 < 2; g0++) {
            MBAR_EXPECT_TX(mb + g0 * 8, GSZ * 8192);
#pragma unroll
            for (int r4 = 0; r4 < GSZ; r4++)
                BULK_G2S(tile0 + (g0 * GSZ + r4) * 8192,
                         src + (size_t)(g0 * GSZ + r4) * (HDIM * 4), 8192,
                         mb + g0 * 8);
        }
    }

    const int lane = t & 31;
    const int wid  = t >> 5;
    // expert index held by this lane after the distribute-reduce: bitrev3(lane)
    const int e_lane = ((lane & 1) << 2) | (lane & 2) | ((lane >> 2) & 1);

    // 32 contiguous gate weights for this thread's 4 h positions -> 16 f32x2.
    long long g2[16];
    {
        const long long* gwp =
            reinterpret_cast<const long long*>(gw) + ((size_t)half * 512 + t) * 16;
#pragma unroll
        for (int i = 0; i < 16; i++) g2[i] = gwp[i];
    }

    for (int g = 0; g < NG; g++) {
        const int slot = g & 1;
        const int par  = (g >> 1) & 1;

        MBAR_WAIT(mb + slot * 8, par);

        // 8 rows per group, in 2 register-friendly sub-batches of 4.
        // keep[i]: row i compressed to one packed reg (experts pair) after
        // shfl levels 0-1.
        long long keep[GSZ];
#pragma unroll
        for (int sb = 0; sb < 2; sb++) {
            float4 v[4];
#pragma unroll
            for (int i = 0; i < 4; i++)
                v[i] = *reinterpret_cast<const float4*>(
                    &s_tile[(slot * GSZ + sb * 4 + i) * 2048 + t * 4]);

            long long acc[4][4];
#pragma unroll
            for (int i = 0; i < 4; i++)
#pragma unroll
                for (int j = 0; j < 4; j++) acc[i][j] = 0;

#pragma unroll
            for (int k = 0; k < 4; k++) {
#pragma unroll
                for (int i = 0; i < 4; i++) {
                    const float vk = (k == 0) ? v[i].x : (k == 1) ? v[i].y
                                   : (k == 2) ? v[i].z : v[i].w;
                    long long pv;
                    PACK2(pv, __float_as_int(vk));
                    FMA2(acc[i][0], pv, g2[k * 4 + 0], acc[i][0]);
                    FMA2(acc[i][1], pv, g2[k * 4 + 1], acc[i][1]);
                    FMA2(acc[i][2], pv, g2[k * 4 + 2], acc[i][2]);
                    FMA2(acc[i][3], pv, g2[k * 4 + 3], acc[i][3]);
                }
            }

            // shfl levels 0-1 (packed): 4 accs -> 1 packed reg per row.
#pragma unroll
            for (int i = 0; i < 4; i++) {
                long long a0 = acc[i][0], a1 = acc[i][1],
                          a2 = acc[i][2], a3 = acc[i][3];
                {   // level 0: xor 1
                    const bool hi = lane & 1;
                    long long s0 = hi ? a0 : a2;
                    long long s1 = hi ? a1 : a3;
                    long long q0 = __shfl_xor_sync(0xffffffffu, s0, 1);
                    long long q1 = __shfl_xor_sync(0xffffffffu, s1, 1);
                    long long k0 = hi ? a2 : a0;
                    long long k1 = hi ? a3 : a1;
                    ADD2(a0, k0, q0);
                    ADD2(a1, k1, q1);
                }
                {   // level 1: xor 2
                    const bool hi = lane & 2;
                    long long s0 = hi ? a0 : a1;
                    long long q0 = __shfl_xor_sync(0xffffffffu, s0, 2);
                    long long k0 = hi ? a1 : a0;
                    ADD2(a0, k0, q0);
                }
                keep[sb * 4 + i] = a0;
            }
        }

        // Tree finish for all 8 rows, interleaved (ILP-8).
        float val[GSZ];
#pragma unroll
        for (int i = 0; i < GSZ; i++) {
            int lo_i, hi_i;
            UNPK2(lo_i, hi_i, keep[i]);
            const float f0 = __int_as_float(lo_i);
            const float f1 = __int_as_float(hi_i);
            const bool hi = lane & 4;
            const float sv = hi ? f0 : f1;
            const float q = __shfl_xor_sync(0xffffffffu, sv, 4);
            val[i] = (hi ? f1 : f0) + q;
        }
#pragma unroll
        for (int i = 0; i < GSZ; i++)
            val[i] += __shfl_xor_sync(0xffffffffu, val[i], 8);
#pragma unroll
        for (int i = 0; i < GSZ; i++)
            val[i] += __shfl_xor_sync(0xffffffffu, val[i], 16);

        if (lane < 8) {
#pragma unroll
            for (int i = 0; i < GSZ; i++)
                s_part[((slot * GSZ + i) * 16 + wid) * 9 + e_lane] = val[i];
        }

        __syncthreads();   // proves: slot fully consumed + s_part complete

        // Refill this slot for group g+2 (overlaps stage-2 + next group).
        if (t == 0 && g + 2 < NG) {
            MBAR_EXPECT_TX(mb + slot * 8, GSZ * 8192);
#pragma unroll
            for (int r4 = 0; r4 < GSZ; r4++)
                BULK_G2S(tile0 + (slot * GSZ + r4) * 8192,
                         src + (size_t)((g + 2) * GSZ + r4) * (HDIM * 4), 8192,
                         mb + slot * 8);
        }

        // stage 2: 64 (row,expert) reductions of 16 warp-partials, 4/warp.
        // s_part is slot-buffered; the g+1 barrier proves stage-2(g) done
        // before slot reuse -> race-free.
#pragma unroll
        for (int it = 0; it < 4; it++) {
            const int pid  = wid + it * 16;   // 0..63
            const int row8 = pid >> 3;
            const int e    = pid & 7;
            float p = (lane < 16)
                    ? s_part[((slot * GSZ + row8) * 16 + lane) * 9 + e] : 0.0f;
            p += __shfl_xor_sync(0xffffffffu, p, 8);
            p += __shfl_xor_sync(0xffffffffu, p, 4);
            p += __shfl_xor_sync(0xffffffffu, p, 2);
            p += __shfl_xor_sync(0xffffffffu, p, 1);
            if (lane == 0)
                g_part[(size_t)(base_row + g * GSZ + row8) * 16 + half * 8 + e] = p;
        }
    }
}

// ---------------------------------------------------------------------------
// Kernel 2: finalize top-2 + combine. PERSISTENT: grid = 1184 blocks (8/SM,
// all co-resident), grid-stride over rows -> no wave transitions, no ragged
// tail. Per row: warp-0 preamble (score = part0+part1+bias, shfl top-2 with
// smallest-index tie-break matching lax.top_k, 2-way softmax == softmax +
// top-2 renorm), then streaming combine out[b,:] = p0*eo[i0,b,:] +
// p1*eo[i1,b,:] with float4 and .cs hints (no reuse).
// ---------------------------------------------------------------------------
#define CBLOCKS 1184
__global__ __launch_bounds__(256) void combine_kernel(
    const float* __restrict__ eo,
    const float* __restrict__ gb,
    float* __restrict__ out)
{
    __shared__ float4 bc;
    const int t = threadIdx.x;

    for (int b = (int)blockIdx.x; b < B_ROWS; b += CBLOCKS) {
        if (t < 32) {
            const int lane = t;
            float s = -3.402823466e38f;
            if (lane < 8)
                s = g_part[(size_t)b * 16 + lane]
                  + g_part[(size_t)b * 16 + 8 + lane] + gb[lane];

            float v1 = s; int i1 = lane;
#pragma unroll
            for (int off = 4; off; off >>= 1) {
                const float ov = __shfl_xor_sync(0xffffffffu, v1, off);
                const int   oi = __shfl_xor_sync(0xffffffffu, i1, off);
                if (ov > v1 || (ov == v1 && oi < i1)) { v1 = ov; i1 = oi; }
            }
            float v2 = (lane == i1) ? -3.402823466e38f : s;
            int i2 = lane;
#pragma unroll
            for (int off = 4; off; off >>= 1) {
                const float ov = __shfl_xor_sync(0xffffffffu, v2, off);
                const int   oi = __shfl_xor_sync(0xffffffffu, i2, off);
                if (ov > v2 || (ov == v2 && oi < i2)) { v2 = ov; i2 = oi; }
            }
            if (lane == 0) {
                const float p1 = 1.0f / (1.0f + expf(v2 - v1));
                bc = make_float4(p1, 1.0f - p1,
                                 __int_as_float(i1), __int_as_float(i2));
            }
        }
        __syncthreads();

        const float4 rg = bc;
        const float p0 = rg.x, p1 = rg.y;
        const int i0 = __float_as_int(rg.z);
        const int i1 = __float_as_int(rg.w);

        const float4* e0 =
            reinterpret_cast<const float4*>(eo + ((size_t)i0 * B_ROWS + b) * HDIM);
        const float4* e1 =
            reinterpret_cast<const float4*>(eo + ((size_t)i1 * B_ROWS + b) * HDIM);
        float4* o = reinterpret_cast<float4*>(out + (size_t)b * HDIM);

        float4 a[4], c[4];
#pragma unroll
        for (int k = 0; k < 4; k++) {
            a[k] = __ldcs(&e0[t + k * 256]);
            c[k] = __ldcs(&e1[t + k * 256]);
        }
#pragma unroll
        for (int k = 0; k < 4; k++) {
            float4 r;
            r.x = p0 * a[k].x + p1 * c[k].x;
            r.y = p0 * a[k].y + p1 * c[k].y;
            r.z = p0 * a[k].z + p1 * c[k].z;
            r.w = p0 * a[k].w + p1 * c[k].w;
            __stcs(&o[t + k * 256], r);
        }
        __syncthreads();   // bc reused next row
    }
}

// ---------------------------------------------------------------------------
// Launch. Inputs (metadata order): hidden_states (B,H) f32, expert_outputs
// (E,B,H) f32, gate_w (H,E) f32, gate_b (E,) f32. Output: (B,H) f32.
// cudaFuncSetAttribute is a non-stream API (not captured) -> capture-safe.
// No allocs, no syncs.
// ---------------------------------------------------------------------------
extern "C" void kernel_launch(void* const* d_in, const int* in_sizes, int n_in,
                              void* d_out, int out_size)
{
    const float* hidden = (const float*)d_in[0];
    const float* eo     = (const float*)d_in[1];
    const float* gw     = (const float*)d_in[2];
    const float* gb     = (const float*)d_in[3];
    float* out = (float*)d_out;

    static bool attr_set = false;
    if (!attr_set) {
        cudaFuncSetAttribute(gate_kernel,
                             cudaFuncAttributeMaxDynamicSharedMemorySize,
                             SMEM_BYTES);
        attr_set = true;
    }

    gate_kernel<<<128, 512, SMEM_BYTES>>>(hidden, gw);
    combine_kernel<<<CBLOCKS, 256>>>(eo, gb, out);
}

// round 16
// speedup vs baseline: 1.0565x; 1.0565x over previous
#include <cuda_runtime.h>
#include <math.h>
#include <stdint.h>

// Problem constants: B=8192 rows, H=4096 hidden, E=8 experts, TOP_K=2. fp32.
#define B_ROWS 8192
#define HDIM   4096
#define RPB    128          // rows per gate block
#define GSZ    8            // rows per pipeline group
#define NG     (RPB / GSZ)  // 16 groups

// Dynamic smem: 2 slots x 8 rows x 8KB + s_part + 2 full-mbarriers
#define SM_TILE_BYTES  (2 * GSZ * 8192)                // 131072
#define SM_PART_OFF    SM_TILE_BYTES
#define SM_PART_BYTES  (2 * 8 * 16 * 9 * 4)            // 9216
#define SM_MBAR_OFF    (SM_PART_OFF + SM_PART_BYTES)   // 140288 (8-aligned)
#define SMEM_BYTES     (SM_MBAR_OFF + 2 * 8)

// Partial gate scores: g_part[row*16 + half*8 + e]  (half = which H-2048 slice)
__device__ float g_part[(size_t)B_ROWS * 16];

// Packed f32x2 helpers (sm_10x packed fp32 pipe, PTX-only)
#define FMA2(d, a, b, c) asm("fma.rn.f32x2 %0, %1, %2, %3;" : "=l"(d) : "l"(a), "l"(b), "l"(c))
#define ADD2(d, a, b)    asm("add.rn.f32x2 %0, %1, %2;"     : "=l"(d) : "l"(a), "l"(b))
#define PACK2(d, x)      asm("mov.b64 %0, {%1, %1};"        : "=l"(d) : "r"(x))
#define UNPK2(lo, hi, s) asm("mov.b64 {%0, %1}, %2;"        : "=r"(lo), "=r"(hi) : "l"(s))

// mbarrier / bulk-copy PTX
#define MBAR_INIT(a, n) \
    asm volatile("mbarrier.init.shared.b64 [%0], %1;" :: "r"(a), "r"(n) : "memory")
#define MBAR_EXPECT_TX(a, n) \
    asm volatile("mbarrier.arrive.expect_tx.shared.b64 _, [%0], %1;" :: "r"(a), "r"(n) : "memory")
#define MBAR_WAIT(a, par) do {                                                   \
    asm volatile(                                                                \
        "{\n\t.reg .pred P1;\n\t"                                                \
        "WL_%=:\n\t"                                                             \
        "mbarrier.try_wait.parity.acquire.cta.shared::cta.b64 P1, [%0], %1, 0x989680;\n\t" \
        "@P1 bra.uni WD_%=;\n\t"                                                 \
        "bra.uni WL_%=;\n\t"                                                     \
        "WD_%=:\n\t}"                                                            \
        :: "r"(a), "r"(par) : "memory");                                         \
} while (0)
#define BULK_G2S(dst, src, bytes, mbar) \
    asm volatile("cp.async.bulk.shared::cta.global.mbarrier::complete_tx::bytes " \
                 "[%0], [%1], %2, [%3];" \
                 :: "r"(dst), "l"(src), "r"(bytes), "r"(mbar) : "memory")

static __device__ __forceinline__ uint32_t smem_u32(const void* p) {
    uint32_t a;
    asm("{ .reg .u64 t; cvta.to.shared.u64 t, %1; cvt.u32.u64 %0, t; }" : "=r"(a) : "l"(p));
    return a;
}

// ---------------------------------------------------------------------------
// Kernel 1: gate partials. grid = 128 blocks x 512 threads (single wave).
// Block (g*2 + half) owns rows [g*128, +128) and H-half [half*2048, +2048).
//
// KEY CHANGE vs R15: EARLY REFILL. Per group, all 8 rows' float4 are loaded
// into registers right after the full-wait; a barrier immediately proves the
// slot is consumed and thread 0 issues the cp.async.bulk refill for group
// g+2 BEFORE the FMA/shfl storm. The 64KB refill DRAM time (~2400 cyc fair
// share) now overlaps the ~1900 cyc of compute instead of serializing after
// it — that serialization was the 35µs-vs-20µs-floor gap in R15.
//
// Consumers: thread t owns h = half*2048 + 4t..+3; its 32 gate weights live
// in 16 packed f32x2 registers, loaded once. Per group: 8 LDS.128, barrier,
// refill, 2 FMA sub-batches of 4 rows (16 chains each) + level-0/1 packed
// shfl compress, 8 interleaved tree finishes, s_part (slot-buffered),
// barrier, stage-2 (64 (row,expert) reductions, 4/warp) -> g_part.
// ---------------------------------------------------------------------------
__global__ __launch_bounds__(512, 1) void gate_kernel(
    const float* __restrict__ hidden,
    const float* __restrict__ gw)     // (H, E) row-major
{
    extern __shared__ __align__(16) unsigned char dynsmem[];
    float* s_tile = reinterpret_cast<float*>(dynsmem);               // [16][2048]
    float* s_part = reinterpret_cast<float*>(dynsmem + SM_PART_OFF); // [2][8][16][9]

    const int t    = threadIdx.x;
    const int half = (int)blockIdx.x & 1;
    const int base_row = ((int)blockIdx.x >> 1) * RPB;

    const uint32_t mb    = smem_u32(dynsmem + SM_MBAR_OFF);  // full[0..1]
    const uint32_t tile0 = smem_u32(dynsmem);
    const char* src = reinterpret_cast<const char*>(
        hidden + (size_t)base_row * HDIM + (size_t)half * 2048);

    if (t == 0) {
        MBAR_INIT(mb + 0, 1);
        MBAR_INIT(mb + 8, 1);
        asm volatile("fence.proxy.async.shared::cta;" ::: "memory");
    }
    __syncthreads();

    // Prologue: thread 0 issues groups 0 and 1 (slots 0 and 1).
    if (t == 0) {
#pragma unroll
        for (int g0 = 0; g0 < 2; g0++) {
            MBAR_EXPECT_TX(mb + g0 * 8, GSZ * 8192);
#pragma unroll
            for (int r4 = 0; r4 < GSZ; r4++)
                BULK_G2S(tile0 + (g0 * GSZ + r4) * 8192,
                         src + (size_t)(g0 * GSZ + r4) * (HDIM * 4), 8192,
                         mb + g0 * 8);
        }
    }

    const int lane = t & 31;
    const int wid  = t >> 5;
    // expert index held by this lane after the distribute-reduce: bitrev3(lane)
    const int e_lane = ((lane & 1) << 2) | (lane & 2) | ((lane >> 2) & 1);

    // 32 contiguous gate weights for this thread's 4 h positions -> 16 f32x2.
    long long g2[16];
    {
        const long long* gwp =
            reinterpret_cast<const long long*>(gw) + ((size_t)half * 512 + t) * 16;
#pragma unroll
        for (int i = 0; i < 16; i++) g2[i] = gwp[i];
    }

    for (int g = 0; g < NG; g++) {
        const int slot = g & 1;
        const int par  = (g >> 1) & 1;

        MBAR_WAIT(mb + slot * 8, par);

        // Pull ALL 8 rows into registers up front.
        float4 v[GSZ];
#pragma unroll
        for (int i = 0; i < GSZ; i++)
            v[i] = *reinterpret_cast<const float4*>(
                &s_tile[(slot * GSZ + i) * 2048 + t * 4]);

        __syncthreads();   // every warp consumed the slot

        // EARLY refill: issue g+2's 64KB now so DRAM overlaps the compute below.
        if (t == 0 && g + 2 < NG) {
            MBAR_EXPECT_TX(mb + slot * 8, GSZ * 8192);
#pragma unroll
            for (int r4 = 0; r4 < GSZ; r4++)
                BULK_G2S(tile0 + (slot * GSZ + r4) * 8192,
                         src + (size_t)((g + 2) * GSZ + r4) * (HDIM * 4), 8192,
                         mb + slot * 8);
        }

        // 2 register-friendly FMA sub-batches of 4 rows; compress each row to
        // one packed reg (experts pair) via shfl levels 0-1.
        long long keep[GSZ];
#pragma unroll
        for (int sb = 0; sb < 2; sb++) {
            long long acc[4][4];
#pragma unroll
            for (int i = 0; i < 4; i++)
#pragma unroll
                for (int j = 0; j < 4; j++) acc[i][j] = 0;

#pragma unroll
            for (int k = 0; k < 4; k++) {
#pragma unroll
                for (int i = 0; i < 4; i++) {
                    const float4 vi = v[sb * 4 + i];
                    const float vk = (k == 0) ? vi.x : (k == 1) ? vi.y
                                   : (k == 2) ? vi.z : vi.w;
                    long long pv;
                    PACK2(pv, __float_as_int(vk));
                    FMA2(acc[i][0], pv, g2[k * 4 + 0], acc[i][0]);
                    FMA2(acc[i][1], pv, g2[k * 4 + 1], acc[i][1]);
                    FMA2(acc[i][2], pv, g2[k * 4 + 2], acc[i][2]);
                    FMA2(acc[i][3], pv, g2[k * 4 + 3], acc[i][3]);
                }
            }

#pragma unroll
            for (int i = 0; i < 4; i++) {
                long long a0 = acc[i][0], a1 = acc[i][1],
                          a2 = acc[i][2], a3 = acc[i][3];
                {   // level 0: xor 1
                    const bool hi = lane & 1;
                    long long s0 = hi ? a0 : a2;
                    long long s1 = hi ? a1 : a3;
                    long long q0 = __shfl_xor_sync(0xffffffffu, s0, 1);
                    long long q1 = __shfl_xor_sync(0xffffffffu, s1, 1);
                    long long k0 = hi ? a2 : a0;
                    long long k1 = hi ? a3 : a1;
                    ADD2(a0, k0, q0);
                    ADD2(a1, k1, q1);
                }
                {   // level 1: xor 2
                    const bool hi = lane & 2;
                    long long s0 = hi ? a0 : a1;
                    long long q0 = __shfl_xor_sync(0xffffffffu, s0, 2);
                    long long k0 = hi ? a1 : a0;
                    ADD2(a0, k0, q0);
                }
                keep[sb * 4 + i] = a0;
            }
        }

        // Tree finish for all 8 rows, interleaved (ILP-8).
        float val[GSZ];
#pragma unroll
        for (int i = 0; i < GSZ; i++) {
            int lo_i, hi_i;
            UNPK2(lo_i, hi_i, keep[i]);
            const float f0 = __int_as_float(lo_i);
            const float f1 = __int_as_float(hi_i);
            const bool hi = lane & 4;
            const float sv = hi ? f0 : f1;
            const float q = __shfl_xor_sync(0xffffffffu, sv, 4);
            val[i] = (hi ? f1 : f0) + q;
        }
#pragma unroll
        for (int i = 0; i < GSZ; i++)
            val[i] += __shfl_xor_sync(0xffffffffu, val[i], 8);
#pragma unroll
        for (int i = 0; i < GSZ; i++)
            val[i] += __shfl_xor_sync(0xffffffffu, val[i], 16);

        if (lane < 8) {
#pragma unroll
            for (int i = 0; i < GSZ; i++)
                s_part[((slot * GSZ + i) * 16 + wid) * 9 + e_lane] = val[i];
        }

        __syncthreads();   // s_part complete

        // stage 2: 64 (row,expert) reductions of 16 warp-partials, 4/warp.
        // s_part is slot-buffered; group g+2's writes happen only after its
        // own first barrier, which every thread reaches after finishing this
        // stage-2 -> race-free.
#pragma unroll
        for (int it = 0; it < 4; it++) {
            const int pid  = wid + it * 16;   // 0..63
            const int row8 = pid >> 3;
            const int e    = pid & 7;
            float p = (lane < 16)
                    ? s_part[((slot * GSZ + row8) * 16 + lane) * 9 + e] : 0.0f;
            p += __shfl_xor_sync(0xffffffffu, p, 8);
            p += __shfl_xor_sync(0xffffffffu, p, 4);
            p += __shfl_xor_sync(0xffffffffu, p, 2);
            p += __shfl_xor_sync(0xffffffffu, p, 1);
            if (lane == 0)
                g_part[(size_t)(base_row + g * GSZ + row8) * 16 + half * 8 + e] = p;
        }
    }
}

// ---------------------------------------------------------------------------
// Kernel 2: finalize top-2 + combine. One block per row (8192 blocks x 256) —
// the persistent grid-stride variant regressed (DRAM 78%->66%) because per-row
// barriers serialized inside each block; independent blocks overlap naturally.
// Warp 0 preamble: score[e] = part[half0] + part[half1] + bias, shfl top-2
// with smallest-index tie-break (matches lax.top_k), 2-way softmax
// (== softmax over 8 + top-2 renorm). Then streaming combine:
// out[b,:] = p0*eo[i0,b,:] + p1*eo[i1,b,:], float4, 8 loads in flight,
// .cs hints (no reuse).
// ---------------------------------------------------------------------------
__global__ __launch_bounds__(256) void combine_kernel(
    const float* __restrict__ eo,
    const float* __restrict__ gb,
    float* __restrict__ out)
{
    const int b = (int)blockIdx.x;
    __shared__ float4 bc;

    if (threadIdx.x < 32) {
        const int lane = threadIdx.x;
        float s = -3.402823466e38f;
        if (lane < 8)
            s = g_part[(size_t)b * 16 + lane] + g_part[(size_t)b * 16 + 8 + lane]
                + gb[lane];

        float v1 = s; int i1 = lane;
#pragma unroll
        for (int off = 4; off; off >>= 1) {
            const float ov = __shfl_xor_sync(0xffffffffu, v1, off);
            const int   oi = __shfl_xor_sync(0xffffffffu, i1, off);
            if (ov > v1 || (ov == v1 && oi < i1)) { v1 = ov; i1 = oi; }
        }
        float v2 = (lane == i1) ? -3.402823466e38f : s;
        int i2 = lane;
#pragma unroll
        for (int off = 4; off; off >>= 1) {
            const float ov = __shfl_xor_sync(0xffffffffu, v2, off);
            const int   oi = __shfl_xor_sync(0xffffffffu, i2, off);
            if (ov > v2 || (ov == v2 && oi < i2)) { v2 = ov; i2 = oi; }
        }
        if (lane == 0) {
            const float p1 = 1.0f / (1.0f + expf(v2 - v1));
            bc = make_float4(p1, 1.0f - p1, __int_as_float(i1), __int_as_float(i2));
        }
    }
    __syncthreads();

    const float4 rg = bc;
    const float p0 = rg.x, p1 = rg.y;
    const int i0 = __float_as_int(rg.z);
    const int i1 = __float_as_int(rg.w);

    const float4* e0 =
        reinterpret_cast<const float4*>(eo + ((size_t)i0 * B_ROWS + b) * HDIM);
    const float4* e1 =
        reinterpret_cast<const float4*>(eo + ((size_t)i1 * B_ROWS + b) * HDIM);
    float4* o = reinterpret_cast<float4*>(out + (size_t)b * HDIM);

    const int t = threadIdx.x;
    float4 a[4], c[4];
#pragma unroll
    for (int k = 0; k < 4; k++) {
        a[k] = __ldcs(&e0[t + k * 256]);
        c[k] = __ldcs(&e1[t + k * 256]);
    }
#pragma unroll
    for (int k = 0; k < 4; k++) {
        float4 r;
        r.x = p0 * a[k].x + p1 * c[k].x;
        r.y = p0 * a[k].y + p1 * c[k].y;
        r.z = p0 * a[k].z + p1 * c[k].z;
        r.w = p0 * a[k].w + p1 * c[k].w;
        __stcs(&o[t + k * 256], r);
    }
}

// ---------------------------------------------------------------------------
// Launch. Inputs (metadata order): hidden_states (B,H) f32, expert_outputs
// (E,B,H) f32, gate_w (H,E) f32, gate_b (E,) f32. Output: (B,H) f32.
// cudaFuncSetAttribute is a non-stream API (not captured) -> capture-safe.
// No allocs, no syncs.
// ---------------------------------------------------------------------------
extern "C" void kernel_launch(void* const* d_in, const int* in_sizes, int n_in,
                              void* d_out, int out_size)
{
    const float* hidden = (const float*)d_in[0];
    const float* eo     = (const float*)d_in[1];
    const float* gw     = (const float*)d_in[2];
    const float* gb     = (const float*)d_in[3];
    float* out = (float*)d_out;

    static bool attr_set = false;
    if (!attr_set) {
        cudaFuncSetAttribute(gate_kernel,
                             cudaFuncAttributeMaxDynamicSharedMemorySize,
                             SMEM_BYTES);
        attr_set = true;
    }

    gate_kernel<<<128, 512, SMEM_BYTES>>>(hidden, gw);
    combine_kernel<<<B_ROWS, 256>>>(eo, gb, out);
}